// round 1
// baseline (speedup 1.0000x reference)
#include <cuda_runtime.h>

// Problem constants
#define Tn   5
#define Cc   3
#define Hh   96
#define Ww   96
#define NHW  24           // 96/4
#define QPB  (Tn*NHW*NHW) // 2880 queries per batch
#define NBt  2
#define NBLK (NBt*QPB)    // 5760 blocks
#define LC   243          // 3*9*9 candidates
#define KS   9            // K-1 neighbors actually used
#define TILE_R 15         // covers [qh-4-3, qh+4+3] span
#define FRAME (Cc*Hh*Ww)
#define VID   (Tn*FRAME)

__device__ float g_partial[NBLK];

__device__ __forceinline__ int refl(int i, int n) {
    i = (i < 0) ? -i : i;
    return (i >= n) ? (2 * (n - 1) - i) : i;
}
__device__ __forceinline__ int clampi(int v, int lo, int hi) {
    return v < lo ? lo : (v > hi ? hi : v);
}

__global__ __launch_bounds__(256) void dnls_main_kernel(
    const float* __restrict__ noisy, const float* __restrict__ deno)
{
    const int bq = blockIdx.x;
    const int b  = bq / QPB;
    const int q  = bq - b * QPB;
    const int qt = q / (NHW * NHW);
    const int r0 = q - qt * (NHW * NHW);
    const int qh = (r0 / NHW) << 2;
    const int qw = (r0 % NHW) << 2;
    const int tid = threadIdx.x;

    __shared__ float tile[3 * Cc * TILE_R * TILE_R]; // [v][c][uh][uw]
    __shared__ float dsh[LC];
    __shared__ float pd[147];
    __shared__ unsigned long long red8[8];
    __shared__ int sel[KS];
    __shared__ float racc8[8];

    const int ft0 = (qt - 1 > 0) ? (qt - 1) : 0;
    const int bh  = ((qh - 4 > 0) ? (qh - 4) : 0) - 3;
    const int bw  = ((qw - 4 > 0) ? (qw - 4) : 0) - 3;

    const float* nb = noisy + (size_t)b * VID;
    const float* db = deno  + (size_t)b * VID;

    // ---- Stage: load 3-frame x 3-ch x 15x15 reflected neighborhood of noisy
    for (int e = tid; e < 3 * Cc * TILE_R * TILE_R; e += 256) {
        int uw = e % TILE_R;
        int t1 = e / TILE_R;
        int uh = t1 % TILE_R;
        int t2 = t1 / TILE_R;
        int c  = t2 % Cc;
        int v  = t2 / Cc;
        int f  = ft0 + v; f = (f > Tn - 1) ? (Tn - 1) : f;
        int hh = refl(bh + uh, Hh);
        int ww = refl(bw + uw, Ww);
        tile[e] = nb[((f * Cc + c) * Hh + hh) * Ww + ww];
    }
    // deno query 7x7x3 patch
    if (tid < 147) {
        int c = tid / 49;
        int r = tid - c * 49;
        int i = r / 7, j = r - (r / 7) * 7;
        int hh = refl(qh + i - 3, Hh);
        int ww = refl(qw + j - 3, Ww);
        pd[tid] = db[((qt * Cc + c) * Hh + hh) * Ww + ww];
    }
    __syncthreads();

    // ---- Phase A: 243 candidate distances (5x5x3 patches), all from SMEM tile
    if (tid < LC) {
        int dt = tid / 81 - 1;
        int r2 = tid - (tid / 81) * 81;
        int dh = r2 / 9 - 4;
        int dw = r2 - (r2 / 9) * 9 - 4;
        int ct = clampi(qt + dt, 0, Tn - 1);
        int ch = clampi(qh + dh, 0, Hh - 1);
        int cw = clampi(qw + dw, 0, Ww - 1);
        int v  = ct - ft0;
        int vq = qt - ft0;
        const float* tc = tile + (v  * Cc) * TILE_R * TILE_R;
        const float* tq = tile + (vq * Cc) * TILE_R * TILE_R;
        const int uh0 = ch - 2 - bh, uw0 = cw - 2 - bw;
        const int vh0 = qh - 2 - bh, vw0 = qw - 2 - bw;
        float acc = 0.f;
        #pragma unroll
        for (int c = 0; c < Cc; c++) {
            #pragma unroll
            for (int i = 0; i < 5; i++) {
                const float* rc = tc + (c * TILE_R + uh0 + i) * TILE_R + uw0;
                const float* rq = tq + (c * TILE_R + vh0 + i) * TILE_R + vw0;
                #pragma unroll
                for (int j = 0; j < 5; j++) {
                    float d = rq[j] - rc[j];   // rq[j]: lane-uniform -> broadcast
                    acc = fmaf(d, d, acc);
                }
            }
        }
        dsh[tid] = (tid == 121) ? __int_as_float(0x7f800000) : acc; // self -> +inf (excluded)
    }
    __syncthreads();

    // ---- Phase B: 9x argmin with (d, idx) packed key; tie -> lower index (matches jax top_k)
    for (int k = 0; k < KS; k++) {
        unsigned long long key = (tid < LC)
            ? ((((unsigned long long)__float_as_uint(dsh[tid])) << 32) | (unsigned)tid)
            : 0xFFFFFFFFFFFFFFFFull;
        #pragma unroll
        for (int off = 16; off; off >>= 1) {
            unsigned long long o = __shfl_down_sync(0xffffffffu, key, off);
            if (o < key) key = o;
        }
        if ((tid & 31) == 0) red8[tid >> 5] = key;
        __syncthreads();
        if (tid < 8) {
            key = red8[tid];
            #pragma unroll
            for (int off = 4; off; off >>= 1) {
                unsigned long long o = __shfl_down_sync(0xffu, key, off);
                if (o < key) key = o;
            }
            if (tid == 0) {
                int widx = (int)(key & 0xffffffffu);
                sel[k] = widx;
                dsh[widx] = __int_as_float(0x7f800000); // remove from pool
            }
        }
        __syncthreads();
    }

    // ---- Phase C: 9 neighbors x 147-dim (7x7x3) deno-vs-noisy distances from tile
    float acc = 0.f;
    for (int item = tid; item < KS * 147; item += 256) {
        int k = item / 147;
        int e = item - k * 147;
        int l = sel[k];
        int dt = l / 81 - 1;
        int r2 = l - (l / 81) * 81;
        int dh = r2 / 9 - 4;
        int dw = r2 - (r2 / 9) * 9 - 4;
        int ct = clampi(qt + dt, 0, Tn - 1);
        int ch = clampi(qh + dh, 0, Hh - 1);
        int cw = clampi(qw + dw, 0, Ww - 1);
        int v  = ct - ft0;
        int c  = e / 49;
        int r3 = e - c * 49;
        int i  = r3 / 7, j = r3 - (r3 / 7) * 7;
        float pv = tile[((v * Cc + c) * TILE_R + (ch + i - 3 - bh)) * TILE_R + (cw + j - 3 - bw)];
        float d = pd[e] - pv;
        acc = fmaf(d, d, acc);
    }
    // deterministic block reduce
    #pragma unroll
    for (int off = 16; off; off >>= 1) acc += __shfl_down_sync(0xffffffffu, acc, off);
    if ((tid & 31) == 0) racc8[tid >> 5] = acc;
    __syncthreads();
    if (tid < 8) {
        acc = racc8[tid];
        #pragma unroll
        for (int off = 4; off; off >>= 1) acc += __shfl_down_sync(0xffu, acc, off);
        if (tid == 0) g_partial[bq] = acc;
    }
}

__global__ void dnls_reduce_kernel(float* __restrict__ out)
{
    __shared__ float buf[8];
    const int tid = threadIdx.x;
    float acc = 0.f;
    for (int i = tid; i < NBLK; i += 256) acc += g_partial[i];
    #pragma unroll
    for (int off = 16; off; off >>= 1) acc += __shfl_down_sync(0xffffffffu, acc, off);
    if ((tid & 31) == 0) buf[tid >> 5] = acc;
    __syncthreads();
    if (tid < 8) {
        acc = buf[tid];
        #pragma unroll
        for (int off = 4; off; off >>= 1) acc += __shfl_down_sync(0xffu, acc, off);
        if (tid == 0) out[0] = acc * (1.0f / (float)(NBt * QPB * KS));
    }
}

extern "C" void kernel_launch(void* const* d_in, const int* in_sizes, int n_in,
                              void* d_out, int out_size)
{
    const float* noisy = (const float*)d_in[0];
    const float* deno  = (const float*)d_in[1];
    // d_in[2] = curr_epoch (unused by the reference forward)
    (void)in_sizes; (void)n_in; (void)out_size;

    dnls_main_kernel<<<NBLK, 256>>>(noisy, deno);
    dnls_reduce_kernel<<<1, 256>>>((float*)d_out);
}